// round 17
// baseline (speedup 1.0000x reference)
#include <cuda_runtime.h>
#include <cuda_fp16.h>
#include <cstdint>

#define DINLINE __device__ __forceinline__

// ======================= scratch (device globals) =======================
__device__ __align__(16) __half g_O1[(size_t)64*65*65*200];
__device__ __align__(16) __half g_O2[(size_t)64*31*31*400];
__device__ __align__(16) __half g_O3[(size_t)64*15*15*800];
__device__ __align__(16) float  g_P4[(size_t)3*10880*32];

__device__ __align__(16) __half g_A1[(size_t)270592*32];
__device__ __align__(16) __half g_B1[(size_t)256*32];
__device__ __align__(16) __half g_B2[(size_t)512*1856];
__device__ __align__(16) __half g_B3[(size_t)896*3648];
__device__ __align__(16) __half g_B4[(size_t)64*7232];

__device__ int g_ctr[2];   // work counters (L2, L3), reset in k_wcvt_all

// ======================= helpers =======================
DINLINE uint32_t smem_u32(const void* p){
    uint32_t a;
    asm("{ .reg .u64 t; cvta.to.shared.u64 t, %1; cvt.u32.u64 %0, t; }" : "=r"(a) : "l"(p));
    return a;
}
DINLINE void cp16(uint32_t dst, const void* src){
    asm volatile("cp.async.cg.shared.global [%0], [%1], 16;" :: "r"(dst), "l"(src));
}
DINLINE void cp16z(uint32_t dst, const void* src, uint32_t srcsize){
    asm volatile("cp.async.cg.shared.global [%0], [%1], 16, %2;" :: "r"(dst), "l"(src), "r"(srcsize));
}
DINLINE void cp_commit(){ asm volatile("cp.async.commit_group;" ::: "memory"); }
DINLINE void cp_wait1(){ asm volatile("cp.async.wait_group 1;" ::: "memory"); }

DINLINE void ldmx4(uint32_t r[4], uint32_t addr){
    asm volatile("ldmatrix.sync.aligned.m8n8.x4.shared.b16 {%0,%1,%2,%3}, [%4];"
        : "=r"(r[0]), "=r"(r[1]), "=r"(r[2]), "=r"(r[3]) : "r"(addr));
}
DINLINE void mma_fp16(float c[4], const uint32_t a[4], uint32_t b0, uint32_t b1){
    asm volatile("mma.sync.aligned.m16n8k16.row.col.f32.f16.f16.f32 "
        "{%0,%1,%2,%3}, {%4,%5,%6,%7}, {%8,%9}, {%0,%1,%2,%3};"
        : "+f"(c[0]), "+f"(c[1]), "+f"(c[2]), "+f"(c[3])
        : "r"(a[0]), "r"(a[1]), "r"(a[2]), "r"(a[3]), "r"(b0), "r"(b1));
}

// ======================= transforms =======================
DINLINE void wcvt_one(const float* W, __half* Bw, int OC, int IC, int Klayer,
                      int Kpad, long idx)
{
    int oc = (int)(idx / Kpad);
    int kk = (int)(idx - (long)oc*Kpad);
    __half out = __float2half_rn(0.f);
    if (oc < OC && kk < Klayer){
        int tap = kk/IC, c = kk - tap*IC;
        out = __float2half_rn(W[((size_t)oc*IC + c)*9 + tap]);
    }
    Bw[idx] = out;
}

static constexpr long WC1 = (long)256*32;
static constexpr long WC2 = WC1 + (long)512*1856;
static constexpr long WC3 = WC2 + (long)896*3648;
static constexpr long WC4 = WC3 + (long)64*7232;

__global__ void k_wcvt_all(const float* __restrict__ w1, const float* __restrict__ w2,
                           const float* __restrict__ w3, const float* __restrict__ w4,
                           __half* __restrict__ B1, __half* __restrict__ B2,
                           __half* __restrict__ B3, __half* __restrict__ B4)
{
    if (blockIdx.x == 0 && threadIdx.x < 2) g_ctr[threadIdx.x] = 0;
    long idx = (long)blockIdx.x*blockDim.x + threadIdx.x;
    if (idx >= WC4) return;
    if (idx < WC1)      wcvt_one(w1, B1, 200, 3,   27,   32,   idx);
    else if (idx < WC2) wcvt_one(w2, B2, 400, 200, 1800, 1856, idx - WC1);
    else if (idx < WC3) wcvt_one(w3, B3, 800, 400, 3600, 3648, idx - WC2);
    else                wcvt_one(w4, B4, 10,  800, 7200, 7232, idx - WC3);
}

__global__ void k_gather1(const float* __restrict__ X, __half* __restrict__ A,
                          const int* __restrict__ selh, const int* __restrict__ selw)
{
    int n = blockIdx.x*blockDim.x + threadIdx.x;
    if (n >= 270592) return;
    __half row[32];
#pragma unroll
    for (int i=0;i<32;i++) row[i] = __float2half_rn(0.f);
    if (n < 270400){
        int b = n / 4225, p = n - b*4225;
        int oy = p/65, ox = p - oy*65;
        int ph = oy*2 + selh[p], pw = ox*2 + selw[p];
        const float* xb = X + (size_t)b*3*132*132 + ph*132 + pw;
#pragma unroll
        for (int ic=0; ic<3; ic++)
#pragma unroll
            for (int ky=0; ky<3; ky++)
#pragma unroll
                for (int kx=0; kx<3; kx++)
                    row[(ky*3 + kx)*3 + ic] =
                        __float2half_rn(xb[(size_t)ic*132*132 + ky*132 + kx]);
    }
    uint4* dst = (uint4*)(A + (size_t)n*32);
    uint4* s = (uint4*)row;
#pragma unroll
    for (int i=0;i<4;i++) dst[i] = s[i];
}

__global__ void k_out4(const float* __restrict__ P4, const float* __restrict__ bias,
                       float* __restrict__ out)
{
    int idx = blockIdx.x*blockDim.x + threadIdx.x;
    if (idx >= 108160) return;
    int n = idx / 10, oc = idx - n*10;
    const size_t ps = (size_t)10880*32;
    float v = P4[(size_t)n*32 + oc] + P4[ps + (size_t)n*32 + oc]
            + P4[2*ps + (size_t)n*32 + oc] + __ldg(&bias[oc]);
    int b = n / 169, p = n - b*169;
    out[(b*10 + oc)*169 + p] = v;
}

// ======================= persistent L1 GEMM (K=32) =======================
static constexpr int SMEM_L1 = 16384 * 4;

__global__ __launch_bounds__(256, 2)
void k_hmma1(const __half* __restrict__ A, const __half* __restrict__ Bw,
             const float* __restrict__ bias, const int* __restrict__ mask,
             __half* __restrict__ Out)
{
    extern __shared__ char smem[];
    const uint32_t sb = smem_u32(smem);
    const int tid = threadIdx.x, lane = tid & 31, warp = tid >> 5;
    const int wm = warp >> 1, wn = warp & 1;

    const int l_row4 = tid >> 2, l_ch4 = tid & 3;
    const uint32_t soff4 = (uint32_t)(l_row4*128 + ((l_ch4 ^ (l_row4&7))<<4));

    {
        const __half* Bg = Bw + (size_t)(blockIdx.x*128 + l_row4)*32 + l_ch4*8;
#pragma unroll
        for (int i=0;i<2;i++) cp16(sb + soff4 + i*8192, Bg + i*64*32);
    }

    const int NBLK = 2114, STEP = gridDim.y;
    auto loadA = [&](int it){
        int nb = blockIdx.y + it*STEP;
        if (nb >= NBLK) return;
        const __half* Ag = A + ((size_t)nb*128 + l_row4)*32 + l_ch4*8;
        uint32_t sA = sb + 16384 + (it%3)*16384;
#pragma unroll
        for (int j=0;j<2;j++) cp16(sA + soff4 + j*8192, Ag + j*64*32);
    };

    loadA(0); cp_commit();
    loadA(1); cp_commit();

    const uint32_t rowA = (uint32_t)((wm*32 + (lane & 15)) * 128);
    const uint32_t rowB = (uint32_t)((wn*64 + (lane & 15)) * 128);
    const uint32_t chbase = (uint32_t)(lane >> 4);
    const uint32_t chxor  = (uint32_t)(lane & 7);
    uint32_t aB[4];
#pragma unroll
    for (int i=0;i<4;i++) aB[i] = sb + rowB + i*16*128;

    const int niter = (NBLK - blockIdx.y + STEP - 1) / STEP;
#pragma unroll 1
    for (int it = 0; it < niter; it++){
        cp_wait1();
        __syncthreads();
        loadA(it+2); cp_commit();

        const uint32_t sA = sb + 16384 + (it%3)*16384;
        const uint32_t aA0 = sA + rowA, aA1 = aA0 + 16*128;

        float c[2][8][4];
#pragma unroll
        for (int i=0;i<2;i++)
#pragma unroll
            for (int j=0;j<8;j++)
#pragma unroll
                for (int k=0;k<4;k++) c[i][j][k] = 0.f;

        uint32_t a[2][2][4], b[2][4][4];
        {
            const uint32_t ch = (chbase ^ chxor) << 4;
            ldmx4(a[0][0], aA0 + ch); ldmx4(a[0][1], aA1 + ch);
#pragma unroll
            for (int i=0;i<4;i++) ldmx4(b[0][i], aB[i] + ch);
        }
#pragma unroll
        for (int ks = 0; ks < 2; ks++){
            const int cur = ks & 1, nxt = cur ^ 1;
            if (ks < 1){
                const uint32_t ch = (((ks+1)*2 + chbase) ^ chxor) << 4;
                ldmx4(a[nxt][0], aA0 + ch); ldmx4(a[nxt][1], aA1 + ch);
#pragma unroll
                for (int i=0;i<4;i++) ldmx4(b[nxt][i], aB[i] + ch);
            }
#pragma unroll
            for (int mi = 0; mi < 2; mi++)
#pragma unroll
                for (int nj = 0; nj < 8; nj++)
                    mma_fp16(c[mi][nj], a[cur][mi],
                             b[cur][nj>>1][nj&1], b[cur][nj>>1][2+(nj&1)]);
        }

        const int nb = blockIdx.y + it*STEP;
        const int gm0 = nb*128 + wm*32;
        const int oc0 = blockIdx.x*128 + wn*64;
#pragma unroll
        for (int mi = 0; mi < 2; mi++){
#pragma unroll
            for (int half = 0; half < 2; half++){
                int n = gm0 + mi*16 + half*8 + (lane >> 2);
                if (n >= 270400) continue;
                int p = n % 4225;
                int mk = mask[p];
#pragma unroll
                for (int nj = 0; nj < 8; nj++){
                    int oc = oc0 + nj*8 + (lane & 3)*2;
                    if (oc < 200){
                        float v0 = (mk ? c[mi][nj][half*2+0] : 0.f) + __ldg(&bias[oc]);
                        float v1 = (mk ? c[mi][nj][half*2+1] : 0.f) + __ldg(&bias[oc+1]);
                        v0 = fmaxf(v0, 0.f); v1 = fmaxf(v1, 0.f);
                        __half2* orow = (__half2*)(Out + (size_t)n * 200 + oc);
                        *orow = __floats2half2_rn(v0, v1);
                    }
                }
            }
        }
    }
}

// ======================= HMMA body (shared by L2/L3 persistent + L4) =======================
static constexpr int STAGE = 32768;
static constexpr int SMEM_HM = 3 * STAGE + 512 + 3712;
static constexpr int SPLITC = 38;

template <int NT, int OUTM>
DINLINE void hmma_body(const __half* __restrict__ B,
                       const float* __restrict__ bias, const int* __restrict__ mask,
                       void* __restrict__ Outv,
                       int nb, int oc_base, int Kpad, int NC, int OC, int P,
                       int Nreal, int relu,
                       const __half* __restrict__ Src,
                       uint32_t sb, const int* s_base, const int* s_off,
                       int ICp, int Klayer)
{
    const int tid = threadIdx.x, lane = tid & 31, warp = tid >> 5;
    const int wm = warp >> 1, wn = warp & 1;

    const long ld = (long)Kpad;
    const int l_row = tid >> 3, l_ch = tid & 7;
    const uint32_t l_soff = (uint32_t)(l_row*128 + ((l_ch ^ (l_row&7))<<4));
    const __half* Bg = B + (size_t)(oc_base + l_row) * ld + l_ch*8;
    const long ld32 = 32*ld;

    const int cbase = (OUTM == 3) ? (int)blockIdx.z * SPLITC : 0;
    const int NCl   = (OUTM == 3) ? min(SPLITC, NC - cbase) : NC;

    auto loadA = [&](int chunk, uint32_t sA){
        int j = chunk*8 + l_ch;
        int k = j << 3;
        uint32_t sz = (k < Klayer) ? 16u : 0u;
        long off = sz ? (long)s_off[j] : 0;
#pragma unroll
        for (int i=0;i<4;i++){
            int row = l_row + i*32;
            const __half* src = Src + (size_t)s_base[row]*ICp + off;
            cp16z(sA + l_soff + i*4096, src, sz);
        }
    };
    auto loadB = [&](int chunk, uint32_t sB){
#pragma unroll
        for (int i=0;i<NT/32;i++) cp16(sB + l_soff + i*4096, Bg + chunk*64 + i*ld32);
    };

    const uint32_t rowA = (uint32_t)((wm*32 + (lane & 15)) * 128);
    const uint32_t rowB = (uint32_t)((wn*(NT/2) + (lane & 15)) * 128);
    const uint32_t chbase = (uint32_t)(lane >> 4);
    const uint32_t chxor  = (uint32_t)(lane & 7);

    constexpr int NJ = NT/16;
    constexpr int NB = (NT >= 64) ? NT/32 : 1;
    float c[2][NJ][4];
#pragma unroll
    for (int i=0;i<2;i++)
#pragma unroll
        for (int j=0;j<NJ;j++)
#pragma unroll
            for (int k=0;k<4;k++) c[i][j][k] = 0.f;

    loadA(cbase, sb);       loadB(cbase, sb + 16384);       cp_commit();
    if (NCl > 1){ loadA(cbase+1, sb + STAGE); loadB(cbase+1, sb + STAGE + 16384); }
    cp_commit();

#pragma unroll 1
    for (int cc = 0; cc < NCl; cc++){
        cp_wait1();
        __syncthreads();
        if (cc + 2 < NCl){
            uint32_t sA = sb + ((cc+2) % 3)*STAGE;
            loadA(cbase+cc+2, sA); loadB(cbase+cc+2, sA + 16384);
        }
        cp_commit();

        const uint32_t sA = sb + (cc % 3)*STAGE;
        const uint32_t sB = sA + 16384;
        const uint32_t aA0 = sA + rowA, aA1 = aA0 + 16*128;
        uint32_t aB[NB];
#pragma unroll
        for (int i=0;i<NB;i++) aB[i] = sB + rowB + i*16*128;

        uint32_t a[2][2][4], b[2][NB][4];
        {
            const uint32_t ch = (chbase ^ chxor) << 4;
            ldmx4(a[0][0], aA0 + ch); ldmx4(a[0][1], aA1 + ch);
#pragma unroll
            for (int i=0;i<NB;i++) ldmx4(b[0][i], aB[i] + ch);
        }
#pragma unroll
        for (int ks = 0; ks < 4; ks++){
            const int cur = ks & 1, nxt = cur ^ 1;
            if (ks < 3){
                const uint32_t ch = (((ks+1)*2 + chbase) ^ chxor) << 4;
                ldmx4(a[nxt][0], aA0 + ch); ldmx4(a[nxt][1], aA1 + ch);
#pragma unroll
                for (int i=0;i<NB;i++) ldmx4(b[nxt][i], aB[i] + ch);
            }
#pragma unroll
            for (int mi = 0; mi < 2; mi++)
#pragma unroll
                for (int nj = 0; nj < NJ; nj++)
                    mma_fp16(c[mi][nj], a[cur][mi],
                             b[cur][(NJ>2)?(nj>>1):0][nj&1],
                             b[cur][(NJ>2)?(nj>>1):0][2+(nj&1)]);
        }
    }

    const int gm0 = nb*128 + wm*32;
    const int oc0 = oc_base + wn*(NT/2);
#pragma unroll
    for (int mi = 0; mi < 2; mi++){
#pragma unroll
        for (int half = 0; half < 2; half++){
            int n = gm0 + mi*16 + half*8 + (lane >> 2);
            if (n >= Nreal) continue;
            int mk = 1;
            if (OUTM != 3 && mask){ int p = n % P; mk = mask[p]; }
#pragma unroll
            for (int nj = 0; nj < NJ; nj++){
                int oc = oc0 + nj*8 + (lane & 3)*2;
                if (OUTM == 3){
                    int pcol = oc - oc_base;
                    float* o = (float*)Outv + (size_t)blockIdx.z*10880*32
                             + (size_t)n*32 + pcol;
                    float2 v = {c[mi][nj][half*2+0], c[mi][nj][half*2+1]};
                    *(float2*)o = v;
                } else if (oc < OC){
                    float v0 = (mk ? c[mi][nj][half*2+0] : 0.f) + __ldg(&bias[oc]);
                    float v1 = (mk ? c[mi][nj][half*2+1] : 0.f) + __ldg(&bias[oc+1]);
                    if (relu){ v0 = fmaxf(v0, 0.f); v1 = fmaxf(v1, 0.f); }
                    __half2* orow = (__half2*)((__half*)Outv + (size_t)n * OC + oc);
                    *orow = __floats2half2_rn(v0, v1);
                }
            }
        }
    }
}

// ---- persistent work-stealing kernel for L2/L3 (OUTM=1) ----
__global__ __launch_bounds__(256, 2)
void k_hmma_p(const __half* __restrict__ B,
              const float* __restrict__ bias, const int* __restrict__ mask,
              void* __restrict__ Outv,
              int gx128, int gxtot, int oc32_base, int nitems, int ctr_slot,
              int Kpad, int NC, int OC, int P, int Nreal,
              const __half* __restrict__ Src, const int* __restrict__ selh,
              const int* __restrict__ selw, int IW, int ICp, int OW,
              int stride, int Klayer)
{
    extern __shared__ char smem[];
    const uint32_t sb = smem_u32(smem);
    int* s_base = (int*)(smem + 3*STAGE);
    int* s_off  = (int*)(smem + 3*STAGE + 512);
    __shared__ int s_work;
    const int tid = threadIdx.x;

    // offset table once per CTA
    for (int j = tid; j < (Klayer >> 3); j += 256){
        int k = j << 3;
        int tap = k / ICp, c = k - tap*ICp;
        int ky = tap/3, kx = tap - 3*ky;
        s_off[j] = (ky*IW + kx)*ICp + c;
    }

    while (true){
        if (tid == 0) s_work = atomicAdd(&g_ctr[ctr_slot], 1);
        __syncthreads();                 // also acts as end-of-item barrier
        const int w = s_work;
        if (w >= nitems) break;
        const int nb  = w / gxtot;
        const int gxi = w - nb*gxtot;

        if (tid < 128){
            int n = nb*128 + tid;
            if (n >= Nreal) n = Nreal - 1;
            int b = n / P, p = n - b*P;
            int oy = p / OW, ox = p - oy*OW;
            int ph = oy*stride + selh[p], pw = ox*stride + selw[p];
            s_base[tid] = (b*IW + ph)*IW + pw;
        }
        __syncthreads();

        if (gxi < gx128)
            hmma_body<128,1>(B, bias, mask, Outv, nb, gxi*128,
                             Kpad, NC, OC, P, Nreal, 1, Src,
                             sb, s_base, s_off, ICp, Klayer);
        else
            hmma_body<32,1>(B, bias, mask, Outv, nb,
                            oc32_base + (gxi - gx128)*32,
                            Kpad, NC, OC, P, Nreal, 1, Src,
                            sb, s_base, s_off, ICp, Klayer);
    }
}

// ---- L4 kernel (grid-dispatched, split-K) ----
__global__ __launch_bounds__(256, 2)
void k_hmma_l4(const __half* __restrict__ B, void* __restrict__ Outv,
               int Kpad, int NC, int P, int Nreal,
               const __half* __restrict__ Src, int IW, int ICp, int OW,
               int Klayer)
{
    extern __shared__ char smem[];
    const uint32_t sb = smem_u32(smem);
    int* s_base = (int*)(smem + 3*STAGE);
    int* s_off  = (int*)(smem + 3*STAGE + 512);
    const int tid = threadIdx.x;

    if (tid < 128){
        int n = blockIdx.y*128 + tid;
        if (n >= Nreal) n = Nreal - 1;
        int b = n / P, p = n - b*P;
        int oy = p / OW, ox = p - oy*OW;
        s_base[tid] = (b*IW + oy)*IW + ox;
    }
    for (int j = tid; j < (Klayer >> 3); j += 256){
        int k = j << 3;
        int tap = k / ICp, c = k - tap*ICp;
        int ky = tap/3, kx = tap - 3*ky;
        s_off[j] = (ky*IW + kx)*ICp + c;
    }
    __syncthreads();

    hmma_body<32,3>(B, nullptr, nullptr, Outv, blockIdx.y, 0,
                    Kpad, NC, 10, P, Nreal, 0, Src,
                    sb, s_base, s_off, ICp, Klayer);
}

// ======================= launch =======================
extern "C" void kernel_launch(void* const* d_in, const int* in_sizes, int n_in,
                              void* d_out, int out_size) {
    const float* x     = (const float*)d_in[0];
    const float* w1    = (const float*)d_in[1];
    const float* b1    = (const float*)d_in[2];
    const float* w2    = (const float*)d_in[3];
    const float* b2    = (const float*)d_in[4];
    const float* w3    = (const float*)d_in[5];
    const float* b3    = (const float*)d_in[6];
    const float* w4    = (const float*)d_in[7];
    const float* b4    = (const float*)d_in[8];
    const int*   selh1 = (const int*)d_in[9];
    const int*   selw1 = (const int*)d_in[10];
    const int*   mask1 = (const int*)d_in[11];
    const int*   selh2 = (const int*)d_in[12];
    const int*   selw2 = (const int*)d_in[13];
    const int*   mask2 = (const int*)d_in[14];
    const int*   selh3 = (const int*)d_in[15];
    const int*   selw3 = (const int*)d_in[16];
    const int*   mask3 = (const int*)d_in[17];

    float *pP4;
    __half *pO1, *pO2, *pO3, *pA1, *pB1, *pB2, *pB3, *pB4;
    cudaGetSymbolAddress((void**)&pO1, g_O1);
    cudaGetSymbolAddress((void**)&pO2, g_O2);
    cudaGetSymbolAddress((void**)&pO3, g_O3);
    cudaGetSymbolAddress((void**)&pP4, g_P4);
    cudaGetSymbolAddress((void**)&pA1, g_A1);
    cudaGetSymbolAddress((void**)&pB1, g_B1);
    cudaGetSymbolAddress((void**)&pB2, g_B2);
    cudaGetSymbolAddress((void**)&pB3, g_B3);
    cudaGetSymbolAddress((void**)&pB4, g_B4);

    cudaFuncSetAttribute((const void*)k_hmma1,
                         cudaFuncAttributeMaxDynamicSharedMemorySize, SMEM_L1);
    cudaFuncSetAttribute((const void*)k_hmma_p,
                         cudaFuncAttributeMaxDynamicSharedMemorySize, SMEM_HM);
    cudaFuncSetAttribute((const void*)k_hmma_l4,
                         cudaFuncAttributeMaxDynamicSharedMemorySize, SMEM_HM);

    // ---- weight conversions + counter reset (one launch) + L1 gather ----
    k_wcvt_all<<<(unsigned)((WC4 + 255) / 256), 256>>>(w1, w2, w3, w4,
                                                       pB1, pB2, pB3, pB4);
    k_gather1<<<(270592 + 255) / 256, 256>>>(x, pA1, selh1, selw1);

    // ---- layer 1: persistent-B GEMM, K=32 ----
    k_hmma1<<<dim3(2, 148), 256, SMEM_L1>>>(pA1, pB1, b1, mask1, pO1);

    // ---- layer 2: persistent work-stealing, items = 482 nb x (3x128 + 1x32) ----
    k_hmma_p<<<296, 256, SMEM_HM>>>(
        pB2, b2, mask2, pO2, 3, 4, 384, 482*4, 0,
        1856, 29, 400, 961, 61504,
        pO1, selh2, selw2, 65, 200, 31, 2, 1800);

    // ---- layer 3: persistent work-stealing, items = 114 nb x (6x128 + 1x32) ----
    k_hmma_p<<<296, 256, SMEM_HM>>>(
        pB3, b3, mask3, pO3, 6, 7, 768, 114*7, 1,
        3648, 57, 800, 225, 14400,
        pO2, selh3, selw3, 31, 400, 15, 2, 3600);

    // ---- layer 4: NT=32 dense GEMM, split-K x3 partials + combine ----
    k_hmma_l4<<<dim3(1, 85, 3), 256, SMEM_HM>>>(
        pB4, pP4, 7232, 113, 169, 10816,
        pO3, 15, 800, 13, 7200);
    k_out4<<<(108160 + 255) / 256, 256>>>(pP4, b4, (float*)d_out);
}